// round 17
// baseline (speedup 1.0000x reference)
#include <cuda_runtime.h>
#include <cuda_fp16.h>
#include <cstdint>

#define N_NODES 50000
#define NNZ     1600000
#define F       128        // D*B
#define M6      6          // stored matrices: x0,t1,t2,t3,t5,t6
#define M_OUT   7
#define U_DIM   64
#define KSPLIT  24
#define KCH     2112       // 24*2112 = 50688 >= 50000
#define GSTEPS  (KCH / 32) // 66

#define GE4     ((NNZ / 4 + 255) / 256)          // 1563 blocks per matrix for edge work
#define GPREP   ((N_NODES * 192 + 255) / 256)    // 37500 blocks for prep work

typedef unsigned int u32;

// ---------------- device scratch (static, no allocation; 16B-aligned for vector casts) ----------------
__device__ __align__(16) __half g_xh[(size_t)M6 * N_NODES * F];       // base matrices in fp16
__device__ __align__(16) __half g_wh[(size_t)N_NODES * F];            // [n][j]: j<64 -> w_ru[:,64+j], j>=64 -> w_c[:,j-64]
__device__ __align__(16) u32    g_csr[2][NNZ];                        // packed: col(16) | half(val)(16)
__device__ __align__(16) int    g_rowptr[2][N_NODES + 4];
__device__ __align__(16) int    g_next[2][N_NODES];
__device__ __align__(16) int    g_cnt[2][N_NODES];                    // zero-init at load; re-zeroed by scan2
__device__ __align__(16) float  g_part[(size_t)KSPLIT * M6 * F * 128];
__device__ __align__(16) float  g_red[(size_t)M6 * F * 128];          // split-K reduced

// ---------------- CSR build ----------------
// scalar reads of harness buffers (alignment not guaranteed), 4 edges per thread
__global__ void hist2(const int* __restrict__ lr, const int* __restrict__ rr) {
    int e0 = (blockIdx.x * blockDim.x + threadIdx.x) * 4;
    if (e0 >= NNZ) return;
    int sel = blockIdx.y;
    const int* rows = sel ? rr : lr;
    #pragma unroll
    for (int q = 0; q < 4; q++) {
        atomicAdd(&g_cnt[sel][__ldg(rows + e0 + q)], 1);
    }
}

// one block per sel; exclusive scan of g_cnt[sel] -> g_rowptr[sel] (+ g_next copy)
// ALSO zeroes g_cnt after reading, so the next kernel_launch call starts clean
// (g_cnt is zero-initialized at module load for the first call).
__global__ void scan2() {
    int sel = blockIdx.x;
    int4* rowptr4 = (int4*)g_rowptr[sel];
    int4* nxt4 = (int4*)g_next[sel];
    int4* cnt4 = (int4*)g_cnt[sel];
    __shared__ int warp_sums[32];
    __shared__ int s_carry;
    int tid = threadIdx.x;  // 1024
    if (tid == 0) s_carry = 0;
    __syncthreads();
    const int NQ = N_NODES / 4;  // 12500
    for (int base = 0; base < NQ; base += 1024) {
        int i = base + tid;
        int4 v = (i < NQ) ? cnt4[i] : make_int4(0, 0, 0, 0);
        int s = v.x + v.y + v.z + v.w;
        int x = s;
        #pragma unroll
        for (int o = 1; o < 32; o <<= 1) {
            int y = __shfl_up_sync(0xffffffffu, x, o);
            if ((tid & 31) >= o) x += y;
        }
        if ((tid & 31) == 31) warp_sums[tid >> 5] = x;
        __syncthreads();
        if (tid < 32) {
            int w = warp_sums[tid];
            #pragma unroll
            for (int o = 1; o < 32; o <<= 1) {
                int y = __shfl_up_sync(0xffffffffu, w, o);
                if (tid >= o) w += y;
            }
            warp_sums[tid] = w;
        }
        __syncthreads();
        int warp_off = (tid >= 32) ? warp_sums[(tid >> 5) - 1] : 0;
        int incl = x + warp_off;
        int carry = s_carry;
        if (i < NQ) {
            int p = carry + incl - s;
            int4 o4;
            o4.x = p;
            o4.y = p + v.x;
            o4.z = p + v.x + v.y;
            o4.w = p + v.x + v.y + v.z;
            rowptr4[i] = o4;
            nxt4[i] = o4;
            cnt4[i] = make_int4(0, 0, 0, 0);   // self-clean for next call
        }
        __syncthreads();
        if (tid == 1023) s_carry = carry + incl;
        __syncthreads();
    }
    if (tid == 0) g_rowptr[sel][N_NODES] = NNZ;
}

// ---------------- fused scatter + prep (independent jobs co-scheduled in one launch) ----------------
// blocks [0, 2*GE4): CSR scatter (sel = b / GE4); blocks [2*GE4, 2*GE4+GPREP): x0 transpose + weight cvt
__global__ void __launch_bounds__(256) scatter_prep(
    const int* __restrict__ lr, const int* __restrict__ lc, const float* __restrict__ lv,
    const int* __restrict__ rr, const int* __restrict__ rc, const float* __restrict__ rv,
    const float* __restrict__ inputs, const float* __restrict__ w_ru, const float* __restrict__ w_c) {
    int b = blockIdx.x;
    if (b < 2 * GE4) {
        int sel = (b >= GE4) ? 1 : 0;
        int e0 = ((b - sel * GE4) * blockDim.x + threadIdx.x) * 4;
        if (e0 >= NNZ) return;
        const int* rows = sel ? rr : lr;
        const int* cols = sel ? rc : lc;
        const float* vals = sel ? rv : lv;
        #pragma unroll
        for (int q = 0; q < 4; q++) {
            int e = e0 + q;
            int r = __ldg(rows + e);
            u32 packed = ((u32)__ldg(cols + e) & 0xffffu)
                       | ((u32)__half_as_ushort(__float2half_rn(__ldg(vals + e))) << 16);
            int p = atomicAdd(&g_next[sel][r], 1);
            g_csr[sel][p] = packed;
        }
    } else {
        int idx = (b - 2 * GE4) * blockDim.x + threadIdx.x;
        if (idx < N_NODES * 64) {
            int bb = idx & 63;
            int n = idx >> 6;
            float vx = __ldg(inputs + ((size_t)bb * N_NODES + n) * 2);
            float vy = __ldg(inputs + ((size_t)bb * N_NODES + n) * 2 + 1);
            g_xh[(size_t)n * F + bb] = __float2half_rn(vx);
            g_xh[(size_t)n * F + 64 + bb] = __float2half_rn(vy);
        } else {
            int id2 = idx - N_NODES * 64;
            if (id2 >= N_NODES * F) return;
            int n = id2 >> 7, j = id2 & 127;
            float v = (j < 64) ? __ldg(w_ru + (size_t)n * 128 + 64 + j)
                               : __ldg(w_c + (size_t)n * 64 + (j - 64));
            g_wh[id2] = __float2half_rn(v);
        }
    }
}

// ---------------- SpMM: warp per row; half-warps process disjoint 16-edge halves ----------------
// 32-edge chunks: lane l loads edge base+l; side 0 (lanes 0-15) consumes edges [0,16),
// side 1 (lanes 16-31) consumes [16,32) via width-16 shuffles. Halves merged by shfl_xor(16).
// HFMA2 inner product, 4-edge fp16 windows into fp32; padding edges have val=0.
__device__ __forceinline__ void spmm_body(int mat, int xi, int oi, int row, int lane) {
    int hl = lane & 15;
    int side = lane >> 4;
    u32 hmask = side ? 0xffff0000u : 0x0000ffffu;
    const uint4* xb = (const uint4*)(g_xh + (size_t)xi * N_NODES * F);
    int e0 = __ldg(&g_rowptr[mat][row]);
    int e1 = __ldg(&g_rowptr[mat][row + 1]);
    float f0x = 0.f, f0y = 0.f, f1x = 0.f, f1y = 0.f;
    float f2x = 0.f, f2y = 0.f, f3x = 0.f, f3y = 0.f;
    const __half2 hz = __float2half2_rn(0.f);

    for (int base = e0; base < e1; base += 32) {
        int n = e1 - base;                 // edges remaining in row (uniform across warp)
        u32 pk = (lane < n) ? __ldg(&g_csr[mat][base + lane]) : 0u;
        int nside = n - (side << 4);       // this side's edge count in chunk
        if (nside > 16) nside = 16;        // (may be <= 0 -> first window breaks)
        #pragma unroll
        for (int w = 0; w < 4; w++) {
            if (w * 4 >= nside) break;
            __half2 a0 = hz, a1 = hz, a2 = hz, a3 = hz;
            #pragma unroll
            for (int k = 0; k < 4; k++) {
                u32 e = __shfl_sync(hmask, pk, w * 4 + k, 16);  // sources within own half
                int c = (int)(e & 0xffffu) << 4;
                __half2 ev = *(__half2*)&e;
                __half2 vv = __high2half2(ev);
                uint4 p = __ldg(xb + c + hl);
                a0 = __hfma2(vv, *(__half2*)&p.x, a0);
                a1 = __hfma2(vv, *(__half2*)&p.y, a1);
                a2 = __hfma2(vv, *(__half2*)&p.z, a2);
                a3 = __hfma2(vv, *(__half2*)&p.w, a3);
            }
            float2 t;
            t = __half22float2(a0); f0x += t.x; f0y += t.y;
            t = __half22float2(a1); f1x += t.x; f1y += t.y;
            t = __half22float2(a2); f2x += t.x; f2y += t.y;
            t = __half22float2(a3); f3x += t.x; f3y += t.y;
        }
    }

    // merge the two halves (warp fully converged here; loop bounds are warp-uniform)
    f0x += __shfl_xor_sync(0xffffffffu, f0x, 16);
    f0y += __shfl_xor_sync(0xffffffffu, f0y, 16);
    f1x += __shfl_xor_sync(0xffffffffu, f1x, 16);
    f1y += __shfl_xor_sync(0xffffffffu, f1y, 16);
    f2x += __shfl_xor_sync(0xffffffffu, f2x, 16);
    f2y += __shfl_xor_sync(0xffffffffu, f2y, 16);
    f3x += __shfl_xor_sync(0xffffffffu, f3x, 16);
    f3y += __shfl_xor_sync(0xffffffffu, f3y, 16);

    if (side == 0) {
        __half2 h0 = __floats2half2_rn(f0x, f0y);
        __half2 h1 = __floats2half2_rn(f1x, f1y);
        __half2 h2 = __floats2half2_rn(f2x, f2y);
        __half2 h3 = __floats2half2_rn(f3x, f3y);
        uint4 pk2; pk2.x = *(u32*)&h0; pk2.y = *(u32*)&h1; pk2.z = *(u32*)&h2; pk2.w = *(u32*)&h3;
        ((uint4*)(g_xh + (size_t)oi * N_NODES * F))[(size_t)row * 16 + hl] = pk2;
    }
}

// block = 256 threads = 8 warps = 8 rows; grid = 6250 exact
__global__ void __launch_bounds__(256, 5) spmm_w(int mat, int xi, int oi) {
    int lane = threadIdx.x & 31;
    int row = (blockIdx.x << 3) + (threadIdx.x >> 5);
    spmm_body(mat, xi, oi, row, lane);
}

// combined: y=0 -> t2 = L t1 ; y=1 -> t3 = R t1
__global__ void __launch_bounds__(256, 5) spmm_dual() {
    int lane = threadIdx.x & 31;
    int row = (blockIdx.x << 3) + (threadIdx.x >> 5);
    if (blockIdx.y == 0) spmm_body(0, 1, 2, row, lane);
    else                 spmm_body(1, 1, 3, row, lane);
}

// ---------------- tensor-core GEMM, split-K over 6 base matrices ----------------
__global__ void __launch_bounds__(256) gemm_h() {
    __shared__ __align__(16) __half As[32 * 128];
    __shared__ __align__(16) __half Bs[32 * 128];
    int ks = blockIdx.x, m = blockIdx.y;
    const __half* A = g_xh + (size_t)m * N_NODES * F;
    int tid = threadIdx.x, lane = tid & 31, wid = tid >> 5;
    int f0w = (wid >> 1) * 32;
    int j0w = (wid & 1) * 64;
    u32 as_base = (u32)__cvta_generic_to_shared(As);
    u32 bs_base = (u32)__cvta_generic_to_shared(Bs);

    float c[2][8][4];
    #pragma unroll
    for (int a = 0; a < 2; a++)
        #pragma unroll
        for (int b = 0; b < 8; b++)
            #pragma unroll
            for (int d = 0; d < 4; d++) c[a][b][d] = 0.f;

    int n0 = ks * KCH;
    int lk0 = tid >> 4, lcf = tid & 15;
    int lk1 = lk0 + 16;
    int soff0 = lk0 * 128 + ((lcf ^ (lk0 & 7)) << 3);
    int soff1 = lk1 * 128 + ((lcf ^ (lk1 & 7)) << 3);

    uint4 ra0, ra1, rb0, rb1;
    const uint4 zz = make_uint4(0, 0, 0, 0);
    {
        int na = n0 + lk0, nbg = n0 + lk1;
        if (na < N_NODES) {
            ra0 = *(const uint4*)(A + (size_t)na * F + lcf * 8);
            rb0 = *(const uint4*)(g_wh + (size_t)na * F + lcf * 8);
        } else { ra0 = zz; rb0 = zz; }
        if (nbg < N_NODES) {
            ra1 = *(const uint4*)(A + (size_t)nbg * F + lcf * 8);
            rb1 = *(const uint4*)(g_wh + (size_t)nbg * F + lcf * 8);
        } else { ra1 = zz; rb1 = zz; }
    }

    int g = lane >> 3, i = lane & 7;

    for (int s = 0; s < GSTEPS; s++) {
        __syncthreads();
        *(uint4*)(As + soff0) = ra0; *(uint4*)(Bs + soff0) = rb0;
        *(uint4*)(As + soff1) = ra1; *(uint4*)(Bs + soff1) = rb1;
        __syncthreads();
        if (s + 1 < GSTEPS) {
            int nb = n0 + (s + 1) * 32;
            int na = nb + lk0, nbg = nb + lk1;
            if (na < N_NODES) {
                ra0 = *(const uint4*)(A + (size_t)na * F + lcf * 8);
                rb0 = *(const uint4*)(g_wh + (size_t)na * F + lcf * 8);
            } else { ra0 = zz; rb0 = zz; }
            if (nbg < N_NODES) {
                ra1 = *(const uint4*)(A + (size_t)nbg * F + lcf * 8);
                rb1 = *(const uint4*)(g_wh + (size_t)nbg * F + lcf * 8);
            } else { ra1 = zz; rb1 = zz; }
        }
        #pragma unroll
        for (int kk = 0; kk < 32; kk += 16) {
            u32 a[2][4];
            #pragma unroll
            for (int mt = 0; mt < 2; mt++) {
                int fb = f0w + mt * 16;
                int k = kk + ((g >> 1) << 3) + i;
                int cf = (fb >> 3) + (g & 1);
                u32 addr = as_base + (u32)((k * 128 + ((cf ^ (k & 7)) << 3)) * 2);
                asm volatile("ldmatrix.sync.aligned.m8n8.x4.trans.shared.b16 {%0,%1,%2,%3}, [%4];"
                    : "=r"(a[mt][0]), "=r"(a[mt][1]), "=r"(a[mt][2]), "=r"(a[mt][3]) : "r"(addr));
            }
            u32 b[8][2];
            #pragma unroll
            for (int np = 0; np < 4; np++) {
                int nb = j0w + np * 16;
                int k = kk + ((g & 1) << 3) + i;
                int cf = (nb >> 3) + (g >> 1);
                u32 addr = bs_base + (u32)((k * 128 + ((cf ^ (k & 7)) << 3)) * 2);
                asm volatile("ldmatrix.sync.aligned.m8n8.x4.trans.shared.b16 {%0,%1,%2,%3}, [%4];"
                    : "=r"(b[np * 2][0]), "=r"(b[np * 2][1]), "=r"(b[np * 2 + 1][0]), "=r"(b[np * 2 + 1][1])
                    : "r"(addr));
            }
            #pragma unroll
            for (int mt = 0; mt < 2; mt++)
                #pragma unroll
                for (int nt = 0; nt < 8; nt++)
                    asm volatile("mma.sync.aligned.m16n8k16.row.col.f32.f16.f16.f32 "
                        "{%0,%1,%2,%3}, {%4,%5,%6,%7}, {%8,%9}, {%0,%1,%2,%3};"
                        : "+f"(c[mt][nt][0]), "+f"(c[mt][nt][1]), "+f"(c[mt][nt][2]), "+f"(c[mt][nt][3])
                        : "r"(a[mt][0]), "r"(a[mt][1]), "r"(a[mt][2]), "r"(a[mt][3]),
                          "r"(b[nt][0]), "r"(b[nt][1]));
        }
    }

    float* P = g_part + ((size_t)ks * M6 + m) * F * 128;
    int fr = lane >> 2, jc = (lane & 3) * 2;
    #pragma unroll
    for (int mt = 0; mt < 2; mt++)
        #pragma unroll
        for (int nt = 0; nt < 8; nt++) {
            int f = f0w + mt * 16 + fr;
            int j = j0w + nt * 8 + jc;
            *(float2*)(P + (size_t)f * 128 + j) = make_float2(c[mt][nt][0], c[mt][nt][1]);
            *(float2*)(P + (size_t)(f + 8) * 128 + j) = make_float2(c[mt][nt][2], c[mt][nt][3]);
        }
}

// ---------------- split-K reduce: g_part -> g_red (coalesced, 98304 threads) ----------------
__global__ void __launch_bounds__(256) reduce_part() {
    int idx = blockIdx.x * blockDim.x + threadIdx.x;  // < M6*F*128
    float s = 0.f;
    #pragma unroll 4
    for (int ks = 0; ks < KSPLIT; ks++) {
        s += g_part[(size_t)ks * (M6 * F * 128) + idx];
    }
    g_red[idx] = s;
}

// ---------------- Chebyshev combos + bias + GRU epilogue (57344 threads) ----------------
// G_m = g_red[m]; outputs (m=0..6):
//   O0=G0  O1=G1  O2=2G2-G0  O3=G3  O4=2G4-G1  O5=G4  O6=2G5-G3
__global__ void __launch_bounds__(256) finish(const float* __restrict__ hx, const float* __restrict__ b_ru,
                                              const float* __restrict__ b_c, float* __restrict__ out) {
    int idx = blockIdx.x * blockDim.x + threadIdx.x;  // over 7*128*64
    if (idx >= M_OUT * F * U_DIM) return;
    int j = idx & 63;
    int f = (idx >> 6) & 127;
    int m = idx >> 13;
    const int srcm[M_OUT] = {0, 1, 2, 3, 4, 4, 5};
    const int subm[M_OUT] = {-1, -1, 0, -1, 1, -1, 3};
    int sm = srcm[m], bm = subm[m];
    const float* Gs = g_red + (size_t)sm * F * 128 + (size_t)f * 128;
    float su = Gs[j];
    float sc = Gs[64 + j];
    if (bm >= 0) {
        const float* Gb = g_red + (size_t)bm * F * 128 + (size_t)f * 128;
        su = 2.f * su - Gb[j];
        sc = 2.f * sc - Gb[64 + j];
    }
    su += __ldg(b_ru + 64 + j);
    sc += __ldg(b_c + j);
    float u = 1.f / (1.f + expf(-su));
    int r = f * M_OUT + m;
    float h = __ldg(hx + (size_t)r * U_DIM + j);
    out[(size_t)r * U_DIM + j] = u * h + (1.f - u) * tanhf(sc);
}

// ---------------- launcher ----------------
extern "C" void kernel_launch(void* const* d_in, const int* in_sizes, int n_in,
                              void* d_out, int out_size) {
    const float* inputs   = (const float*)d_in[0];
    const float* hx       = (const float*)d_in[1];
    const float* w_ru     = (const float*)d_in[2];
    const float* b_ru     = (const float*)d_in[3];
    const float* w_c      = (const float*)d_in[4];
    const float* b_c      = (const float*)d_in[5];
    const float* lap_vals = (const float*)d_in[6];
    const float* rw_vals  = (const float*)d_in[7];
    const int*   lrows    = (const int*)d_in[8];
    const int*   lcols    = (const int*)d_in[9];
    const int*   rrows    = (const int*)d_in[10];
    const int*   rcols    = (const int*)d_in[11];
    float* out = (float*)d_out;

    const int TB = 256;
    const int gSp = N_NODES / 8;  // 6250 exact (1 row per warp, 8 warps per block)

    // CSR build (g_cnt is clean: zero-init at load, re-zeroed by scan2 each call)
    hist2<<<dim3(GE4, 2), TB>>>(lrows, rrows);
    scan2<<<2, 1024>>>();
    scatter_prep<<<2 * GE4 + GPREP, TB>>>(lrows, lcols, lap_vals, rrows, rcols, rw_vals,
                                          inputs, w_ru, w_c);

    // SpMM chain: t1 = L x0; {t2 = L t1, t3 = R t1}; t5 = R t3; t6 = R t5
    spmm_w<<<gSp, 256>>>(0, 0, 1);
    spmm_dual<<<dim3(gSp, 2), 256>>>();
    spmm_w<<<gSp, 256>>>(1, 3, 4);
    spmm_w<<<gSp, 256>>>(1, 4, 5);

    // tensor-core GEMM over 6 matrices + parallel reduce + fused combos/epilogue
    gemm_h<<<dim3(KSPLIT, M6), 256>>>();
    reduce_part<<<(M6 * F * 128) / TB, TB>>>();
    finish<<<(M_OUT * F * U_DIM + TB - 1) / TB, TB>>>(hx, b_ru, b_c, out);
}